// round 1
// baseline (speedup 1.0000x reference)
#include <cuda_runtime.h>

#define TT 48
#define SS 1024
#define BB 256
#define TAG_START 45
#define TAG_STOP  46

typedef unsigned long long u64;

// ---- packed f32x2 helpers (Blackwell) ----
__device__ __forceinline__ u64 ffma2(u64 a, u64 b, u64 c){
    u64 d; asm("fma.rn.f32x2 %0, %1, %2, %3;" : "=l"(d) : "l"(a), "l"(b), "l"(c)); return d;
}
__device__ __forceinline__ u64 fadd2(u64 a, u64 b){
    u64 d; asm("add.rn.f32x2 %0, %1, %2;" : "=l"(d) : "l"(a), "l"(b)); return d;
}
__device__ __forceinline__ u64 pack2(float lo, float hi){
    u64 d; asm("mov.b64 %0, {%1, %2};" : "=l"(d) : "f"(lo), "f"(hi)); return d;
}
__device__ __forceinline__ void unpack2(u64 v, float& lo, float& hi){
    asm("mov.b64 {%0, %1}, %2;" : "=f"(lo), "=f"(hi) : "l"(v));
}

// One step of the CRF forward recursion in probability space.
// sc holds scores RELATIVE to accumulated 'offset'. p = exp(sc) shared via psh.
// new[j] = log( sum_k W[j][k] * p[k] ) + f[j]; masked blend; renorm by new[0].
#define CRF_STEP(FX, FY, M, PB) do {                                          \
    float px = __expf(sc.x);                                                  \
    float py = __expf(sc.y);                                                  \
    if (act) *(float2*)&psh[PB][j0] = make_float2(px, py);                    \
    __syncwarp();                                                             \
    u64 A0=0ull, A1=0ull, C0=0ull, C1=0ull;                                   \
    _Pragma("unroll")                                                         \
    for (int q = 0; q < 12; q++){                                             \
        ulonglong2 P = *(const ulonglong2*)&psh[PB][4*q];                     \
        A0 = ffma2(W0[2*q],   P.x, A0);                                       \
        A1 = ffma2(W1[2*q],   P.x, A1);                                       \
        C0 = ffma2(W0[2*q+1], P.y, C0);                                       \
        C1 = ffma2(W1[2*q+1], P.y, C1);                                       \
    }                                                                         \
    u64 S0 = fadd2(A0, C0), S1 = fadd2(A1, C1);                               \
    float l0, h0h, l1, h1h;                                                   \
    unpack2(S0, l0, h0h); unpack2(S1, l1, h1h);                               \
    float h0 = fmaxf(l0 + h0h, 1e-30f);                                       \
    float h1 = fmaxf(l1 + h1h, 1e-30f);                                       \
    float n0 = __logf(h0) + (FX);                                             \
    float n1 = __logf(h1) + (FY);                                             \
    float om = 1.0f - (M);                                                    \
    n0 = n0*(M) + sc.x*om;                                                    \
    n1 = n1*(M) + sc.y*om;                                                    \
    float r = __shfl_sync(0xffffffffu, n0, 0);                                \
    sc.x = n0 - r; sc.y = n1 - r;                                             \
    offset += (double)r;                                                      \
} while(0)

__global__ void __launch_bounds__(32) crf_kernel(
    const float* __restrict__ feats,
    const float* __restrict__ masks,
    const void*  __restrict__ tagsp,
    const float* __restrict__ trans,
    float*       __restrict__ out)
{
    __shared__ __align__(16) float psh[2][64];
    const int lane = threadIdx.x;
    const int b    = blockIdx.x;
    const int j0   = 2*lane, j1 = j0 + 1;     // two tags per lane (f32x2)
    const bool act = (lane < 24);             // lanes 24..31 are padding (T=48)

    // -------- detect tag element width (int32 vs int64) --------
    const int* t32 = (const int*)tagsp;
    int det = t32[1] | t32[3] | t32[5] | t32[7] | t32[9] | t32[11] | t32[13] | t32[15];
    const bool is64 = (det == 0);
    const long long* t64 = (const long long*)tagsp;

    // -------- W = exp(transitions), packed as k-pairs in registers --------
    u64 W0[24], W1[24];
    #pragma unroll
    for (int kk = 0; kk < 24; kk++){
        float a0 = 0.f, a1 = 0.f, c0 = 0.f, c1 = 0.f;
        if (j0 < TT){ float2 t = *(const float2*)&trans[j0*TT + 2*kk]; a0 = __expf(t.x); a1 = __expf(t.y); }
        if (j1 < TT){ float2 t = *(const float2*)&trans[j1*TT + 2*kk]; c0 = __expf(t.x); c1 = __expf(t.y); }
        W0[kk] = pack2(a0, a1);
        W1[kk] = pack2(c0, c1);
    }
    float ts0 = (j0 < TT) ? trans[TAG_STOP*TT + j0] : -3.0e38f;
    float ts1 = (j1 < TT) ? trans[TAG_STOP*TT + j1] : -3.0e38f;

    const float* fB = feats + (size_t)b * SS * TT;
    const float* mB = masks + (size_t)b * SS;

    float2 sc;
    sc.x = (j0 == TAG_START) ? 0.f : -10000.f;
    sc.y = (j1 == TAG_START) ? 0.f : -10000.f;
    double offset = 0.0;

    // -------- software prefetch: 4 steps of feats (float2/lane) + masks (float4) --------
    float2 fb0[4], fb1[4];
    float4 mb0, mb1;
    #pragma unroll
    for (int u = 0; u < 4; u++)
        fb0[u] = act ? *(const float2*)&fB[u*TT + j0] : make_float2(0.f, 0.f);
    mb0 = *(const float4*)&mB[0];

    // -------- main scan: 8 steps per iteration, ping-pong p-buffer & prefetch --------
    for (int sb = 0; sb < SS; sb += 8){
        #pragma unroll
        for (int u = 0; u < 4; u++)
            fb1[u] = act ? *(const float2*)&fB[(sb+4+u)*TT + j0] : make_float2(0.f, 0.f);
        mb1 = *(const float4*)&mB[sb+4];

        CRF_STEP(fb0[0].x, fb0[0].y, mb0.x, 0);
        CRF_STEP(fb0[1].x, fb0[1].y, mb0.y, 1);
        CRF_STEP(fb0[2].x, fb0[2].y, mb0.z, 0);
        CRF_STEP(fb0[3].x, fb0[3].y, mb0.w, 1);

        if (sb + 8 < SS){
            #pragma unroll
            for (int u = 0; u < 4; u++)
                fb0[u] = act ? *(const float2*)&fB[(sb+8+u)*TT + j0] : make_float2(0.f, 0.f);
            mb0 = *(const float4*)&mB[sb+8];
        }

        CRF_STEP(fb1[0].x, fb1[0].y, mb1.x, 0);
        CRF_STEP(fb1[1].x, fb1[1].y, mb1.y, 1);
        CRF_STEP(fb1[2].x, fb1[2].y, mb1.z, 0);
        CRF_STEP(fb1[3].x, fb1[3].y, mb1.w, 1);
    }

    // -------- log_z = logsumexp_j(score[j] + trans[STOP][j]) + offset --------
    float v0 = act ? (sc.x + ts0) : -3.0e38f;
    float v1 = act ? (sc.y + ts1) : -3.0e38f;
    float mx = fmaxf(v0, v1);
    #pragma unroll
    for (int o = 16; o; o >>= 1) mx = fmaxf(mx, __shfl_xor_sync(0xffffffffu, mx, o));
    float es = __expf(v0 - mx) + __expf(v1 - mx);
    #pragma unroll
    for (int o = 16; o; o >>= 1) es += __shfl_xor_sync(0xffffffffu, es, o);
    double logz = offset + (double)mx + (double)__logf(es);

    // -------- gold score (emissions + transitions along the tagged path) --------
    float g = 0.f, lenf = 0.f;
    for (int si = lane; si < SS; si += 32){
        float m = mB[si];
        long long base = (long long)b * SS + si;
        int tg = is64 ? (int)t64[base] : t32[base];
        int pv = (si == 0) ? TAG_START : (is64 ? (int)t64[base-1] : t32[base-1]);
        float e  = fB[si*TT + tg];
        float tr = trans[tg*TT + pv];
        g    += (e + tr) * m;
        lenf += m;
    }
    #pragma unroll
    for (int o = 16; o; o >>= 1){
        g    += __shfl_xor_sync(0xffffffffu, g,    o);
        lenf += __shfl_xor_sync(0xffffffffu, lenf, o);
    }
    int len  = (int)lenf;
    int last = (len == 0) ? TAG_START
                          : (is64 ? (int)t64[(long long)b*SS + len - 1]
                                  : t32[(long long)b*SS + len - 1]);
    g += trans[TAG_STOP*TT + last];

    if (lane == 0) out[b] = (float)(logz - (double)g);
}

extern "C" void kernel_launch(void* const* d_in, const int* in_sizes, int n_in,
                              void* d_out, int out_size)
{
    const float* feats = (const float*)d_in[0];
    const float* masks = (const float*)d_in[1];
    const void*  tags  = (const void*) d_in[2];
    const float* trans = (const float*)d_in[3];
    float* out = (float*)d_out;
    crf_kernel<<<BB, 32>>>(feats, masks, tags, trans, out);
}